// round 4
// baseline (speedup 1.0000x reference)
#include <cuda_runtime.h>
#include <stdint.h>

#define N_LEVELS 16
#define BATCH (1 << 20)
#define DENSE_TOTAL 1023633   // sum of res^3 for levels 0..7 (== OFFSETS[8])

// 2x2 (y,z) quad per cell: {cell(y,z), (y,z+1), (y+1,z), (y+1,z+1)}, 32 bytes
struct __align__(32) Quad { float4 ab; float4 cd; };
__device__ Quad g_dense[DENSE_TOTAL];

__host__ __device__ __forceinline__ constexpr int lvl_res(int l) {
    constexpr int r[N_LEVELS] = {16, 20, 25, 32, 40, 50, 64, 80, 101, 128, 161, 203, 256, 322, 406, 512};
    return r[l];
}
__host__ __device__ __forceinline__ constexpr int lvl_off(int l) {
    constexpr int o[N_LEVELS + 1] = {0, 4096, 12096, 27721, 60489, 124489, 249489, 511633, 1023633,
                                     1547921, 2072209, 2596497, 3120785, 3645073, 4169361, 4693649, 5217937};
    return o[l];
}
__host__ __device__ __forceinline__ constexpr bool lvl_dense(int l) {
    long long r = lvl_res(l);
    long long size = lvl_off(l + 1) - lvl_off(l);
    return r * r * r <= size;
}

// 256-bit global load (sm_100+)
struct F8 { float v[8]; };
__device__ __forceinline__ F8 ldg256(const Quad* p) {
    F8 q;
    asm("ld.global.nc.v8.f32 {%0,%1,%2,%3,%4,%5,%6,%7}, [%8];"
        : "=f"(q.v[0]), "=f"(q.v[1]), "=f"(q.v[2]), "=f"(q.v[3]),
          "=f"(q.v[4]), "=f"(q.v[5]), "=f"(q.v[6]), "=f"(q.v[7])
        : "l"(p));
    return q;
}

// ── prologue: build (y,z)-quad dense table ─────────────────────────────────
__global__ __launch_bounds__(256) void repack_kernel(const float2* __restrict__ emb)
{
    for (int i = blockIdx.x * blockDim.x + threadIdx.x; i < DENSE_TOTAL;
         i += gridDim.x * blockDim.x) {
        // find level (compile-time-unrolled search)
        int res = 0;
#pragma unroll
        for (int l = 0; l < 8; ++l)
            if (i >= lvl_off(l) && i < lvl_off(l + 1)) res = lvl_res(l);
        // neighbors: z+1 -> +1, y+1 -> +res  (edge quads hold garbage, never read)
        float2 a = __ldg(emb + i);
        float2 b = __ldg(emb + i + 1);
        float2 c = __ldg(emb + i + res);          // stays within table bounds
        float2 d = __ldg(emb + i + res + 1);
        Quad q;
        q.ab = make_float4(a.x, a.y, b.x, b.y);
        q.cd = make_float4(c.x, c.y, d.x, d.y);
        g_dense[i] = q;
    }
}

// ── main kernel ────────────────────────────────────────────────────────────
__global__ __launch_bounds__(256) void hashgrid_kernel(
    const float* __restrict__ xyz,
    const float2* __restrict__ emb,
    const float* __restrict__ mn,
    const float* __restrict__ mx,
    float* __restrict__ out)
{
    __shared__ float4 s_out[256][8];   // 32 KB, bank-swizzled

    const int tid = threadIdx.x;
    const int b = blockIdx.x * blockDim.x + tid;   // BATCH == grid*block exactly

    const float inv_x = 1.0f / (mx[0] - mn[0]);
    const float inv_y = 1.0f / (mx[1] - mn[1]);
    const float inv_z = 1.0f / (mx[2] - mn[2]);
    const float xn = (xyz[3 * b + 0] - mn[0]) * inv_x;
    const float yn = (xyz[3 * b + 1] - mn[1]) * inv_y;
    const float zn = (xyz[3 * b + 2] - mn[2]) * inv_z;

    float pend0 = 0.0f, pend1 = 0.0f;

#pragma unroll
    for (int l = 0; l < N_LEVELS; ++l) {
        const int      res   = lvl_res(l);
        const int      off   = lvl_off(l);
        const bool     dense = lvl_dense(l);
        const uint32_t size  = (uint32_t)(lvl_off(l + 1) - off);  // 2^19 for hashed levels

        const float sc = (float)(res - 1);
        const float px = xn * sc, py = yn * sc, pz = zn * sc;

        float fx = floorf(px), fy = floorf(py), fz = floorf(pz);
        const float hi = (float)(res - 2);
        fx = fminf(fmaxf(fx, 0.0f), hi);
        fy = fminf(fmaxf(fy, 0.0f), hi);
        fz = fminf(fmaxf(fz, 0.0f), hi);

        const float wx = px - fx, wy = py - fy, wz = pz - fz;
        const uint32_t ix0 = (uint32_t)fx, iy0 = (uint32_t)fy, iz0 = (uint32_t)fz;

        float a0 = 0.0f, a1 = 0.0f;

        if (dense) {
            // one LDG.256 per x-corner: covers all 4 (y,z) corners
            const uint32_t r2 = (uint32_t)(res * res);
            const uint32_t base = iy0 * (uint32_t)res + iz0;
            const F8 qa = ldg256(&g_dense[off + ix0 * r2 + base]);
            const F8 qb = ldg256(&g_dense[off + (ix0 + 1u) * r2 + base]);

            const float wy0 = 1.0f - wy, wz0 = 1.0f - wz;
            const float w00 = wy0 * wz0;   // (y0,z0) -> ab.xy
            const float w01 = wy0 * wz;    // (y0,z1) -> ab.zw
            const float w10 = wy  * wz0;   // (y1,z0) -> cd.xy
            const float w11 = wy  * wz;    // (y1,z1) -> cd.zw

            const float mx0 = 1.0f - wx;
            float t0, t1;
            t0 = w00 * qa.v[0]; t0 = fmaf(w01, qa.v[2], t0); t0 = fmaf(w10, qa.v[4], t0); t0 = fmaf(w11, qa.v[6], t0);
            t1 = w00 * qa.v[1]; t1 = fmaf(w01, qa.v[3], t1); t1 = fmaf(w10, qa.v[5], t1); t1 = fmaf(w11, qa.v[7], t1);
            a0 = mx0 * t0; a1 = mx0 * t1;
            t0 = w00 * qb.v[0]; t0 = fmaf(w01, qb.v[2], t0); t0 = fmaf(w10, qb.v[4], t0); t0 = fmaf(w11, qb.v[6], t0);
            t1 = w00 * qb.v[1]; t1 = fmaf(w01, qb.v[3], t1); t1 = fmaf(w10, qb.v[5], t1); t1 = fmaf(w11, qb.v[7], t1);
            a0 = fmaf(wx, t0, a0); a1 = fmaf(wx, t1, a1);
        } else {
            uint32_t idx[8];
#pragma unroll
            for (int c = 0; c < 8; ++c) {
                const uint32_t cx = (c >> 2) & 1u;
                const uint32_t cy = (c >> 1) & 1u;
                const uint32_t cz = c & 1u;
                uint32_t id = (ix0 + cx) ^ ((iy0 + cy) * 2654435761u) ^ ((iz0 + cz) * 805459861u);
                idx[c] = id & (size - 1u);   // size is 2^19 for all hashed levels
            }
            float2 f[8];
#pragma unroll
            for (int c = 0; c < 8; ++c)
                f[c] = __ldg(emb + off + idx[c]);

#pragma unroll
            for (int c = 0; c < 8; ++c) {
                const float mxw = ((c >> 2) & 1) ? wx : (1.0f - wx);
                const float myw = ((c >> 1) & 1) ? wy : (1.0f - wy);
                const float mzw = (c & 1)        ? wz : (1.0f - wz);
                const float w = mxw * myw * mzw;
                a0 = fmaf(w, f[c].x, a0);
                a1 = fmaf(w, f[c].y, a1);
            }
        }

        if ((l & 1) == 0) {
            pend0 = a0; pend1 = a1;
        } else {
            const int c = l >> 1;
            s_out[tid][c ^ (tid & 7)] = make_float4(pend0, pend1, a0, a1);
        }
    }

    __syncthreads();

    // coalesced write-out: block covers 2048 consecutive float4s of out
    float4* o4 = (float4*)out + (size_t)blockIdx.x * 2048;
#pragma unroll
    for (int k = 0; k < 8; ++k) {
        const int f = tid + k * 256;       // 0..2047
        const int r = f >> 3, c = f & 7;
        o4[f] = s_out[r][c ^ (r & 7)];
    }
}

extern "C" void kernel_launch(void* const* d_in, const int* in_sizes, int n_in,
                              void* d_out, int out_size)
{
    const float*  xyz = (const float*)d_in[0];
    const float2* emb = (const float2*)d_in[1];
    const float*  mn  = (const float*)d_in[2];
    const float*  mx  = (const float*)d_in[3];
    float* out = (float*)d_out;

    repack_kernel<<<2048, 256>>>(emb);

    const int threads = 256;
    const int blocks  = BATCH / threads;   // exact
    hashgrid_kernel<<<blocks, threads>>>(xyz, emb, mn, mx, out);
}

// round 6
// speedup vs baseline: 1.1851x; 1.1851x over previous
#include <cuda_runtime.h>
#include <stdint.h>

#define N_LEVELS 16
#define BATCH (1 << 20)
#define DENSE_TOTAL 1023633   // sum of res^3 for levels 0..7 (== OFFSETS[8])

// 2x2 (y,z) quad per cell: {cell(y,z), (y,z+1), (y+1,z), (y+1,z+1)}, 32 bytes
struct __align__(32) Quad { float4 ab; float4 cd; };
__device__ Quad g_dense[DENSE_TOTAL];

__host__ __device__ __forceinline__ constexpr int lvl_res(int l) {
    constexpr int r[N_LEVELS] = {16, 20, 25, 32, 40, 50, 64, 80, 101, 128, 161, 203, 256, 322, 406, 512};
    return r[l];
}
__host__ __device__ __forceinline__ constexpr int lvl_off(int l) {
    constexpr int o[N_LEVELS + 1] = {0, 4096, 12096, 27721, 60489, 124489, 249489, 511633, 1023633,
                                     1547921, 2072209, 2596497, 3120785, 3645073, 4169361, 4693649, 5217937};
    return o[l];
}
__host__ __device__ __forceinline__ constexpr bool lvl_dense(int l) {
    long long r = lvl_res(l);
    long long size = lvl_off(l + 1) - lvl_off(l);
    return r * r * r <= size;
}

// 256-bit global load (sm_100+)
struct F8 { float v[8]; };
__device__ __forceinline__ F8 ldg256(const Quad* p) {
    F8 q;
    asm("ld.global.nc.v8.f32 {%0,%1,%2,%3,%4,%5,%6,%7}, [%8];"
        : "=f"(q.v[0]), "=f"(q.v[1]), "=f"(q.v[2]), "=f"(q.v[3]),
          "=f"(q.v[4]), "=f"(q.v[5]), "=f"(q.v[6]), "=f"(q.v[7])
        : "l"(p));
    return q;
}

// ── prologue: build (y,z)-quad dense table ─────────────────────────────────
__global__ __launch_bounds__(256) void repack_kernel(const float2* __restrict__ emb)
{
    for (int i = blockIdx.x * blockDim.x + threadIdx.x; i < DENSE_TOTAL;
         i += gridDim.x * blockDim.x) {
        int res = 0;
#pragma unroll
        for (int l = 0; l < 8; ++l)
            if (i >= lvl_off(l) && i < lvl_off(l + 1)) res = lvl_res(l);
        // neighbors: z+1 -> +1, y+1 -> +res  (edge quads hold garbage, never read)
        float2 a = __ldg(emb + i);
        float2 b = __ldg(emb + i + 1);
        float2 c = __ldg(emb + i + res);          // stays within table bounds
        float2 d = __ldg(emb + i + res + 1);
        Quad q;
        q.ab = make_float4(a.x, a.y, b.x, b.y);
        q.cd = make_float4(c.x, c.y, d.x, d.y);
        g_dense[i] = q;
    }
}

// ── main kernel ────────────────────────────────────────────────────────────
__global__ __launch_bounds__(256) void hashgrid_kernel(
    const float* __restrict__ xyz,
    const float2* __restrict__ emb,
    const float* __restrict__ mn,
    const float* __restrict__ mx,
    float* __restrict__ out)
{
    const int b = blockIdx.x * blockDim.x + threadIdx.x;   // grid*block == BATCH exactly

    const float inv_x = 1.0f / (mx[0] - mn[0]);
    const float inv_y = 1.0f / (mx[1] - mn[1]);
    const float inv_z = 1.0f / (mx[2] - mn[2]);
    const float xn = (xyz[3 * b + 0] - mn[0]) * inv_x;
    const float yn = (xyz[3 * b + 1] - mn[1]) * inv_y;
    const float zn = (xyz[3 * b + 2] - mn[2]) * inv_z;

    float4* o4 = (float4*)(out + (size_t)b * (2 * N_LEVELS));

    float pend0 = 0.0f, pend1 = 0.0f;

#pragma unroll
    for (int l = 0; l < N_LEVELS; ++l) {
        const int      res   = lvl_res(l);
        const int      off   = lvl_off(l);
        const bool     dense = lvl_dense(l);
        const uint32_t size  = (uint32_t)(lvl_off(l + 1) - off);  // 2^19 for hashed levels

        const float sc = (float)(res - 1);
        const float px = xn * sc, py = yn * sc, pz = zn * sc;

        float fx = floorf(px), fy = floorf(py), fz = floorf(pz);
        const float hi = (float)(res - 2);
        fx = fminf(fmaxf(fx, 0.0f), hi);
        fy = fminf(fmaxf(fy, 0.0f), hi);
        fz = fminf(fmaxf(fz, 0.0f), hi);

        const float wx = px - fx, wy = py - fy, wz = pz - fz;
        const uint32_t ix0 = (uint32_t)fx, iy0 = (uint32_t)fy, iz0 = (uint32_t)fz;

        float a0, a1;

        if (dense) {
            // one LDG.256 per x-corner: covers all 4 (y,z) corners
            const uint32_t r2 = (uint32_t)(res * res);
            const uint32_t base = iy0 * (uint32_t)res + iz0;
            const F8 qa = ldg256(&g_dense[off + ix0 * r2 + base]);
            const F8 qb = ldg256(&g_dense[off + (ix0 + 1u) * r2 + base]);

            const float wy0 = 1.0f - wy, wz0 = 1.0f - wz;
            const float w00 = wy0 * wz0;   // (y0,z0) -> ab.xy
            const float w01 = wy0 * wz;    // (y0,z1) -> ab.zw
            const float w10 = wy  * wz0;   // (y1,z0) -> cd.xy
            const float w11 = wy  * wz;    // (y1,z1) -> cd.zw

            const float mx0 = 1.0f - wx;
            float t0, t1;
            t0 = w00 * qa.v[0]; t0 = fmaf(w01, qa.v[2], t0); t0 = fmaf(w10, qa.v[4], t0); t0 = fmaf(w11, qa.v[6], t0);
            t1 = w00 * qa.v[1]; t1 = fmaf(w01, qa.v[3], t1); t1 = fmaf(w10, qa.v[5], t1); t1 = fmaf(w11, qa.v[7], t1);
            a0 = mx0 * t0; a1 = mx0 * t1;
            t0 = w00 * qb.v[0]; t0 = fmaf(w01, qb.v[2], t0); t0 = fmaf(w10, qb.v[4], t0); t0 = fmaf(w11, qb.v[6], t0);
            t1 = w00 * qb.v[1]; t1 = fmaf(w01, qb.v[3], t1); t1 = fmaf(w10, qb.v[5], t1); t1 = fmaf(w11, qb.v[7], t1);
            a0 = fmaf(wx, t0, a0); a1 = fmaf(wx, t1, a1);
        } else {
            uint32_t idx[8];
#pragma unroll
            for (int c = 0; c < 8; ++c) {
                const uint32_t cx = (c >> 2) & 1u;
                const uint32_t cy = (c >> 1) & 1u;
                const uint32_t cz = c & 1u;
                uint32_t id = (ix0 + cx) ^ ((iy0 + cy) * 2654435761u) ^ ((iz0 + cz) * 805459861u);
                idx[c] = id & (size - 1u);   // size is 2^19 for all hashed levels
            }
            float2 f[8];
#pragma unroll
            for (int c = 0; c < 8; ++c)
                f[c] = __ldg(emb + off + idx[c]);

            a0 = 0.0f; a1 = 0.0f;
#pragma unroll
            for (int c = 0; c < 8; ++c) {
                const float mxw = ((c >> 2) & 1) ? wx : (1.0f - wx);
                const float myw = ((c >> 1) & 1) ? wy : (1.0f - wy);
                const float mzw = (c & 1)        ? wz : (1.0f - wz);
                const float w = mxw * myw * mzw;
                a0 = fmaf(w, f[c].x, a0);
                a1 = fmaf(w, f[c].y, a1);
            }
        }

        if ((l & 1) == 0) {
            pend0 = a0; pend1 = a1;
        } else {
            o4[l >> 1] = make_float4(pend0, pend1, a0, a1);  // one STG.128 per 2 levels
        }
    }
}

extern "C" void kernel_launch(void* const* d_in, const int* in_sizes, int n_in,
                              void* d_out, int out_size)
{
    const float*  xyz = (const float*)d_in[0];
    const float2* emb = (const float2*)d_in[1];
    const float*  mn  = (const float*)d_in[2];
    const float*  mx  = (const float*)d_in[3];
    float* out = (float*)d_out;

    repack_kernel<<<2048, 256>>>(emb);

    const int threads = 256;
    const int blocks  = BATCH / threads;   // exact
    hashgrid_kernel<<<blocks, threads>>>(xyz, emb, mn, mx, out);
}